// round 5
// baseline (speedup 1.0000x reference)
#include <cuda_runtime.h>
#include <math.h>
#include <stdint.h>

// Problem constants
#define Bc 2
#define Tc 2048
#define Dc 1024
#define Hc 16
#define DHc 64
#define NBc 32
#define ROWS (Bc*Tc)          // 4096

// ---------------- scratch ----------------
__device__ float g_h   [ (size_t)ROWS * Dc ];
__device__ float g_tmp [ (size_t)ROWS * Dc ];
__device__ float g_q   [ (size_t)ROWS * Dc ];
__device__ float g_k   [ (size_t)ROWS * Dc ];
__device__ float g_v   [ (size_t)ROWS * Dc ];
__device__ float g_attn[ (size_t)ROWS * Dc ];
__device__ float g_x2  [ (size_t)ROWS * Dc ];
__device__ float g_ffn [ (size_t)ROWS * 4 * Dc ];
// pre-swizzled weights (tf32): [n_tile][k_tile][2048] tile images
__device__ float g_wq_t[ (size_t)Dc * Dc ];
__device__ float g_wk_t[ (size_t)Dc * Dc ];
__device__ float g_wv_t[ (size_t)Dc * Dc ];
__device__ float g_wo_t[ (size_t)Dc * Dc ];
__device__ float g_w1_t[ (size_t)Dc * 4 * Dc ];
__device__ float g_w2_t[ (size_t)Dc * 4 * Dc ];

// ---------------- helpers ----------------
__device__ __forceinline__ float to_tf32(float x)
{
    uint32_t u;
    asm("cvt.rna.tf32.f32 %0, %1;" : "=r"(u) : "f"(x));
    return __uint_as_float(u);
}

__device__ __forceinline__ void mma8(float c[4],
    float a0, float a1, float a2, float a3, float b0, float b1)
{
    asm volatile(
        "mma.sync.aligned.m16n8k8.row.col.f32.tf32.tf32.f32 "
        "{%0,%1,%2,%3}, {%4,%5,%6,%7}, {%8,%9}, {%0,%1,%2,%3};"
        : "+f"(c[0]), "+f"(c[1]), "+f"(c[2]), "+f"(c[3])
        : "r"(__float_as_uint(a0)), "r"(__float_as_uint(a1)),
          "r"(__float_as_uint(a2)), "r"(__float_as_uint(a3)),
          "r"(__float_as_uint(b0)), "r"(__float_as_uint(b1)));
}

// A-operand layout (row-major m x k16): [r][ 4*((k&3)^(r&3)) + (k>>2) ]
__device__ __forceinline__ int a_idx(int r, int k, int stride)
{
    return r * stride + ((k >> 4) << 4) + 4 * (((k & 3) ^ (r & 3))) + ((k >> 2) & 3);
}
// B-operand layout used in attention (unchanged, proven)
__device__ __forceinline__ int b_idx(int n, int k, int stride)
{
    return n * stride + ((k >> 4) << 4)
         + 4 * (((k & 3) ^ (n & 3) ^ ((n >> 2) & 3))) + ((k >> 2) & 3);
}

__device__ __forceinline__ void cp_async16(uint32_t smem_dst, const void* gptr)
{
    asm volatile("cp.async.cg.shared.global [%0], [%1], 16;"
                 :: "r"(smem_dst), "l"(gptr));
}
__device__ __forceinline__ void cp_commit()  { asm volatile("cp.async.commit_group;"); }
__device__ __forceinline__ void cp_wait0()   { asm volatile("cp.async.wait_group 0;" ::: "memory"); }

__device__ __forceinline__ float gelu_f(float v)
{
    return 0.5f * v * (1.0f + erff(v * 0.70710678118654752f));
}

// ---------------- weight prep: W[K][N] -> swizzled tiles ----------------------
// out tile (nt, kt): dst[nl*16 + 4*((k&3)^(nl&3)) + (k>>2)] = tf32(W[kt*16+k][nt*128+nl])
__global__ void __launch_bounds__(128) prep_w(const float* __restrict__ W,
                                              float* __restrict__ out, int K, int N)
{
    __shared__ float s[16][132];
    int kt = blockIdx.x, nt = blockIdx.y, tid = threadIdx.x;
    int ktiles = K / 16;
    for (int e = tid; e < 2048; e += 128) {
        int kk = e >> 7, nl = e & 127;
        s[kk][nl] = to_tf32(W[(size_t)(kt * 16 + kk) * N + nt * 128 + nl]);
    }
    __syncthreads();
    float* dst = out + ((size_t)nt * ktiles + kt) * 2048;
    #pragma unroll
    for (int j = 0; j < 4; j++) {
        int u = tid + 128 * j;          // unit 0..511
        int nl = u >> 2, g = u & 3;
        int c = g ^ (nl & 3);
        float4 v;
        v.x = s[c][nl];
        v.y = s[c + 4][nl];
        v.z = s[c + 8][nl];
        v.w = s[c + 12][nl];
        *(float4*)&dst[u * 4] = v;
    }
}

// ---------------- LayerNorm ----------------
__global__ void __launch_bounds__(256) ln_kernel(const float* __restrict__ x,
                                                 const float* __restrict__ g,
                                                 const float* __restrict__ b,
                                                 float* __restrict__ o)
{
    __shared__ float sred[16];
    int row = blockIdx.x;
    int tid = threadIdx.x;
    const float* xr = x + (size_t)row * Dc;
    float4 v = *(const float4*)&xr[tid * 4];
    float s  = v.x + v.y + v.z + v.w;
    float s2 = v.x*v.x + v.y*v.y + v.z*v.z + v.w*v.w;
    #pragma unroll
    for (int off = 16; off; off >>= 1) {
        s  += __shfl_xor_sync(0xffffffffu, s,  off);
        s2 += __shfl_xor_sync(0xffffffffu, s2, off);
    }
    if ((tid & 31) == 0) { sred[tid >> 5] = s; sred[8 + (tid >> 5)] = s2; }
    __syncthreads();
    float S = 0.f, S2 = 0.f;
    #pragma unroll
    for (int i = 0; i < 8; i++) { S += sred[i]; S2 += sred[8 + i]; }
    float mean = S * (1.0f / Dc);
    float var  = S2 * (1.0f / Dc) - mean * mean;
    float rstd = rsqrtf(var + 1e-5f);
    float4 gv = *(const float4*)&g[tid * 4];
    float4 bv = *(const float4*)&b[tid * 4];
    float4 ov;
    ov.x = (v.x - mean) * rstd * gv.x + bv.x;
    ov.y = (v.y - mean) * rstd * gv.y + bv.y;
    ov.z = (v.z - mean) * rstd * gv.z + bv.z;
    ov.w = (v.w - mean) * rstd * gv.w + bv.w;
    *(float4*)&o[(size_t)row * Dc + tid * 4] = ov;
}

// ---------------- TF32 GEMM: 128x128 CTA, 4 warps of 64x64, cp.async B -------
template<bool GELU>
__global__ void __launch_bounds__(128, 2) gemm_tc(
    const float* __restrict__ A, const float* __restrict__ Bt,
    const float* __restrict__ bias, const float* __restrict__ res,
    float* __restrict__ C, int M, int N, int K)
{
    __shared__ float sA[2][128 * 16];
    __shared__ float sB[2][128 * 16];

    int tid  = threadIdx.x;
    int lane = tid & 31;
    int warp = tid >> 5;
    int q4 = lane & 3, rr = lane >> 2;
    int wm = (warp & 1) * 64;
    int wn = (warp >> 1) * 64;
    int bm = blockIdx.y * 128, bn = blockIdx.x * 128;

    int ktiles = K / 16;
    // A load mapping: thread -> rows ar, ar+32, ar+64, ar+96; cols ac..ac+3
    int ar = tid >> 2;            // 0..31
    int ac = (tid & 3) * 4;       // k>>2 = tid&3
    const float* Aptr = A + (size_t)(bm + ar) * K + ac;
    // B: pre-swizzled tiles, 2048 floats each
    const float* BtBase = Bt + ((size_t)(bn >> 7) * ktiles) * 2048;

    uint32_t sB_u32 = (uint32_t)__cvta_generic_to_shared(&sB[0][0]);

    float acc[4][8][4];
    #pragma unroll
    for (int i = 0; i < 4; i++)
        #pragma unroll
        for (int j = 0; j < 8; j++)
            #pragma unroll
            for (int r = 0; r < 4; r++) acc[i][j][r] = 0.f;

    int axor = ar & 3;            // same for ar+32/64/96
    int qk = tid & 3;             // k>>2 inner offset
    // store bases for the 4 rows
    int sb0 = ar * 16 + qk;
    int sb1 = (ar + 32) * 16 + qk;
    int sb2 = (ar + 64) * 16 + qk;
    int sb3 = (ar + 96) * 16 + qk;

    // prologue: tile 0
    {
        #pragma unroll
        for (int j = 0; j < 4; j++)
            cp_async16(sB_u32 + (tid * 64 + j * 16), BtBase + tid * 16 + j * 4);
        cp_commit();
        float4 a0 = *(const float4*)(Aptr);
        float4 a1 = *(const float4*)(Aptr + (size_t)32 * K);
        float4 a2 = *(const float4*)(Aptr + (size_t)64 * K);
        float4 a3 = *(const float4*)(Aptr + (size_t)96 * K);
        float v0[4] = {a0.x, a0.y, a0.z, a0.w};
        float v1[4] = {a1.x, a1.y, a1.z, a1.w};
        float v2[4] = {a2.x, a2.y, a2.z, a2.w};
        float v3[4] = {a3.x, a3.y, a3.z, a3.w};
        #pragma unroll
        for (int j = 0; j < 4; j++) {
            int off = 4 * (j ^ axor);
            sA[0][sb0 + off] = to_tf32(v0[j]);
            sA[0][sb1 + off] = to_tf32(v1[j]);
            sA[0][sb2 + off] = to_tf32(v2[j]);
            sA[0][sb3 + off] = to_tf32(v3[j]);
        }
        cp_wait0();
    }
    __syncthreads();

    int agrp = 4 * (q4 ^ (rr & 3));

    for (int t = 0; t < ktiles; t++) {
        int buf = t & 1;
        bool pref = (t + 1 < ktiles);
        float4 a0, a1, a2, a3;
        if (pref) {
            int nb = buf ^ 1;
            #pragma unroll
            for (int j = 0; j < 4; j++)
                cp_async16(sB_u32 + (nb * 8192 + tid * 64 + j * 16),
                           BtBase + (size_t)(t + 1) * 2048 + tid * 16 + j * 4);
            cp_commit();
            const float* Ap = Aptr + (t + 1) * 16;
            a0 = *(const float4*)(Ap);
            a1 = *(const float4*)(Ap + (size_t)32 * K);
            a2 = *(const float4*)(Ap + (size_t)64 * K);
            a3 = *(const float4*)(Ap + (size_t)96 * K);
        }

        // B fragments: 8 x LDS128 (covers both k-steps)
        float4 fb[8];
        #pragma unroll
        for (int ni = 0; ni < 8; ni++) {
            int n0 = wn + ni * 8 + rr;
            fb[ni] = *(float4*)&sB[buf][n0 * 16 + 4 * (q4 ^ (n0 & 3))];
        }

        #pragma unroll
        for (int mi = 0; mi < 4; mi++) {
            int r0 = wm + mi * 16 + rr;
            float4 lo = *(float4*)&sA[buf][r0 * 16 + agrp];
            float4 hi = *(float4*)&sA[buf][(r0 + 8) * 16 + agrp];
            #pragma unroll
            for (int ni = 0; ni < 8; ni++) {
                mma8(acc[mi][ni], lo.x, hi.x, lo.y, hi.y, fb[ni].x, fb[ni].y);
                mma8(acc[mi][ni], lo.z, hi.z, lo.w, hi.w, fb[ni].z, fb[ni].w);
            }
        }

        if (pref) {
            int nb = buf ^ 1;
            float v0[4] = {a0.x, a0.y, a0.z, a0.w};
            float v1[4] = {a1.x, a1.y, a1.z, a1.w};
            float v2[4] = {a2.x, a2.y, a2.z, a2.w};
            float v3[4] = {a3.x, a3.y, a3.z, a3.w};
            float* dA = &sA[nb][0];
            #pragma unroll
            for (int j = 0; j < 4; j++) {
                int off = 4 * (j ^ axor);
                dA[sb0 + off] = to_tf32(v0[j]);
                dA[sb1 + off] = to_tf32(v1[j]);
                dA[sb2 + off] = to_tf32(v2[j]);
                dA[sb3 + off] = to_tf32(v3[j]);
            }
            cp_wait0();
        }
        __syncthreads();
    }

    // epilogue
    #pragma unroll
    for (int mi = 0; mi < 4; mi++) {
        int row = bm + wm + mi * 16 + rr;
        #pragma unroll
        for (int ni = 0; ni < 8; ni++) {
            int col = bn + wn + ni * 8 + 2 * q4;
            float2 bb = *(const float2*)&bias[col];
            float2 r01 = make_float2(acc[mi][ni][0] + bb.x, acc[mi][ni][1] + bb.y);
            float2 r23 = make_float2(acc[mi][ni][2] + bb.x, acc[mi][ni][3] + bb.y);
            if (GELU) {
                r01.x = gelu_f(r01.x); r01.y = gelu_f(r01.y);
                r23.x = gelu_f(r23.x); r23.y = gelu_f(r23.y);
            }
            if (res) {
                float2 v0 = *(const float2*)&res[(size_t)row * N + col];
                float2 v1 = *(const float2*)&res[(size_t)(row + 8) * N + col];
                r01.x += v0.x; r01.y += v0.y;
                r23.x += v1.x; r23.y += v1.y;
            }
            *(float2*)&C[(size_t)row * N + col] = r01;
            *(float2*)&C[(size_t)(row + 8) * N + col] = r23;
        }
    }
}

// ---------------- RoPE + transpose -------------------
__global__ void __launch_bounds__(256) rope_kernel(
    const float* __restrict__ in, const float* __restrict__ cosb,
    const float* __restrict__ sinb, float* __restrict__ out, int applyRope)
{
    int idx = blockIdx.x * blockDim.x + threadIdx.x;
    int i = idx & 31;
    int h = (idx >> 5) & 15;
    int t = (idx >> 9) & 2047;
    int b = idx >> 20;
    const float2 xv = *(const float2*)(in + ((((size_t)b*Tc + t)*Hc + h) * DHc) + 2*i);
    float o1, o2;
    if (applyRope) {
        size_t ci = (((size_t)b*Hc + h)*Tc + t) * NBc + i;
        float c = cosb[ci], s = sinb[ci];
        o1 = xv.x * c - xv.y * s;
        o2 = xv.x * s + xv.y * c;
    } else {
        o1 = xv.x; o2 = xv.y;
    }
    *(float2*)(out + ((((size_t)b*Hc + h)*Tc + t) * DHc) + 2*i) = make_float2(o1, o2);
}

// ---------------- Tensor-core flash attention (round-3, proven) --------------
#define ASTR 80

__global__ void __launch_bounds__(256) attn_tc(
    const float* __restrict__ Q, const float* __restrict__ K,
    const float* __restrict__ V, float* __restrict__ O)
{
    extern __shared__ float sm[];
    float* sQ  = sm;
    float* sP  = sm + 128 * ASTR;
    float* sKt = sm + 256 * ASTR;
    float* sVt = sKt + 64 * ASTR;

    int tid = threadIdx.x, lane = tid & 31, warp = tid >> 5;
    int q4 = lane & 3, rr = lane >> 2;
    int bh = blockIdx.y;
    int b = bh >> 4, h = bh & 15;
    int qb = gridDim.x - 1 - blockIdx.x;

    const float* Qb = Q + ((size_t)bh * Tc + (size_t)qb * 128) * DHc;
    const float* Kb = K + (size_t)bh * Tc * DHc;
    const float* Vb = V + (size_t)bh * Tc * DHc;

    #pragma unroll
    for (int jj = 0; jj < 8; jj++) {
        int f4 = tid + 256 * jj;
        int r = f4 >> 4, kb = (f4 & 15) * 4;
        float4 qv = *(const float4*)&Qb[r * 64 + kb];
        sQ[a_idx(r, kb + 0, ASTR)] = to_tf32(qv.x * 0.125f);
        sQ[a_idx(r, kb + 1, ASTR)] = to_tf32(qv.y * 0.125f);
        sQ[a_idx(r, kb + 2, ASTR)] = to_tf32(qv.z * 0.125f);
        sQ[a_idx(r, kb + 3, ASTR)] = to_tf32(qv.w * 0.125f);
    }

    float m0 = -1e30f, m1 = -1e30f, l0 = 0.f, l1 = 0.f;
    float o[8][4];
    #pragma unroll
    for (int ni = 0; ni < 8; ni++)
        #pragma unroll
        for (int j = 0; j < 4; j++) o[ni][j] = 0.f;

    int r0 = 16 * warp + rr;
    int rowg = qb * 128 + r0;
    int agrp = 4 * (q4 ^ (r0 & 3));

    int nkt = 2 * qb + 2;
    for (int kt = 0; kt < nkt; kt++) {
        __syncthreads();
        const float* Kt = Kb + (size_t)kt * 64 * DHc;
        const float* Vt = Vb + (size_t)kt * 64 * DHc;
        #pragma unroll
        for (int jj = 0; jj < 4; jj++) {
            int f4 = tid + 256 * jj;
            int n = f4 >> 4, kb = (f4 & 15) * 4;
            float4 kv = *(const float4*)&Kt[n * 64 + kb];
            sKt[b_idx(n, kb + 0, ASTR)] = to_tf32(kv.x);
            sKt[b_idx(n, kb + 1, ASTR)] = to_tf32(kv.y);
            sKt[b_idx(n, kb + 2, ASTR)] = to_tf32(kv.z);
            sKt[b_idx(n, kb + 3, ASTR)] = to_tf32(kv.w);
            float4 vv = *(const float4*)&Vt[n * 64 + kb];
            sVt[b_idx(kb + 0, n, ASTR)] = to_tf32(vv.x);
            sVt[b_idx(kb + 1, n, ASTR)] = to_tf32(vv.y);
            sVt[b_idx(kb + 2, n, ASTR)] = to_tf32(vv.z);
            sVt[b_idx(kb + 3, n, ASTR)] = to_tf32(vv.w);
        }
        __syncthreads();

        float s[8][4];
        #pragma unroll
        for (int ni = 0; ni < 8; ni++)
            #pragma unroll
            for (int j = 0; j < 4; j++) s[ni][j] = 0.f;

        #pragma unroll
        for (int ch = 0; ch < 4; ch++) {
            float4 lo = *(float4*)&sQ[r0 * ASTR + ch * 16 + agrp];
            float4 hi = *(float4*)&sQ[(r0 + 8) * ASTR + ch * 16 + agrp];
            #pragma unroll
            for (int ni = 0; ni < 8; ni++) {
                int n0 = ni * 8 + rr;
                float4 fb = *(float4*)&sKt[n0 * ASTR + ch * 16
                                + 4 * (q4 ^ (n0 & 3) ^ ((n0 >> 2) & 3))];
                mma8(s[ni], lo.x, hi.x, lo.y, hi.y, fb.x, fb.y);
                mma8(s[ni], lo.z, hi.z, lo.w, hi.w, fb.z, fb.w);
            }
        }

        if (kt >= 2 * qb) {
            #pragma unroll
            for (int ni = 0; ni < 8; ni++) {
                int colg = kt * 64 + ni * 8 + 2 * q4;
                if (colg     > rowg)     s[ni][0] = -1e30f;
                if (colg + 1 > rowg)     s[ni][1] = -1e30f;
                if (colg     > rowg + 8) s[ni][2] = -1e30f;
                if (colg + 1 > rowg + 8) s[ni][3] = -1e30f;
            }
        }

        float mx0 = -1e30f, mx1 = -1e30f;
        #pragma unroll
        for (int ni = 0; ni < 8; ni++) {
            mx0 = fmaxf(mx0, fmaxf(s[ni][0], s[ni][1]));
            mx1 = fmaxf(mx1, fmaxf(s[ni][2], s[ni][3]));
        }
        mx0 = fmaxf(mx0, __shfl_xor_sync(0xffffffffu, mx0, 1));
        mx0 = fmaxf(mx0, __shfl_xor_sync(0xffffffffu, mx0, 2));
        mx1 = fmaxf(mx1, __shfl_xor_sync(0xffffffffu, mx1, 1));
        mx1 = fmaxf(mx1, __shfl_xor_sync(0xffffffffu, mx1, 2));
        float mn0 = fmaxf(m0, mx0), mn1 = fmaxf(m1, mx1);
        float al0 = __expf(m0 - mn0), al1 = __expf(m1 - mn1);
        m0 = mn0; m1 = mn1;

        float sum0 = 0.f, sum1 = 0.f;
        #pragma unroll
        for (int ni = 0; ni < 8; ni++) {
            int kl = ni * 8 + 2 * q4;
            float p0 = __expf(s[ni][0] - m0);
            float p1 = __expf(s[ni][1] - m0);
            float p2 = __expf(s[ni][2] - m1);
            float p3 = __expf(s[ni][3] - m1);
            sum0 += p0 + p1; sum1 += p2 + p3;
            sP[a_idx(r0,     kl,     ASTR)] = p0;
            sP[a_idx(r0,     kl + 1, ASTR)] = p1;
            sP[a_idx(r0 + 8, kl,     ASTR)] = p2;
            sP[a_idx(r0 + 8, kl + 1, ASTR)] = p3;
        }
        sum0 += __shfl_xor_sync(0xffffffffu, sum0, 1);
        sum0 += __shfl_xor_sync(0xffffffffu, sum0, 2);
        sum1 += __shfl_xor_sync(0xffffffffu, sum1, 1);
        sum1 += __shfl_xor_sync(0xffffffffu, sum1, 2);
        l0 = l0 * al0 + sum0;
        l1 = l1 * al1 + sum1;

        #pragma unroll
        for (int ni = 0; ni < 8; ni++) {
            o[ni][0] *= al0; o[ni][1] *= al0;
            o[ni][2] *= al1; o[ni][3] *= al1;
        }
        __syncwarp();

        #pragma unroll
        for (int ch = 0; ch < 4; ch++) {
            float4 lo = *(float4*)&sP[r0 * ASTR + ch * 16 + agrp];
            float4 hi = *(float4*)&sP[(r0 + 8) * ASTR + ch * 16 + agrp];
            #pragma unroll
            for (int ni = 0; ni < 8; ni++) {
                int n0 = ni * 8 + rr;
                float4 fb = *(float4*)&sVt[n0 * ASTR + ch * 16
                                + 4 * (q4 ^ (n0 & 3) ^ ((n0 >> 2) & 3))];
                mma8(o[ni], lo.x, hi.x, lo.y, hi.y, fb.x, fb.y);
                mma8(o[ni], lo.z, hi.z, lo.w, hi.w, fb.z, fb.w);
            }
        }
    }

    float inv0 = 1.f / l0, inv1 = 1.f / l1;
    int t0 = qb * 128 + r0;
    #pragma unroll
    for (int ni = 0; ni < 8; ni++) {
        int dh = ni * 8 + 2 * q4;
        *(float2*)&O[((((size_t)b * Tc + t0) * Hc + h) * DHc) + dh] =
            make_float2(o[ni][0] * inv0, o[ni][1] * inv0);
        *(float2*)&O[((((size_t)b * Tc + t0 + 8) * Hc + h) * DHc) + dh] =
            make_float2(o[ni][2] * inv1, o[ni][3] * inv1);
    }
}

// ---------------- launch ----------------
extern "C" void kernel_launch(void* const* d_in, const int* in_sizes, int n_in,
                              void* d_out, int out_size)
{
    const float* x    = (const float*)d_in[0];
    const float* cosb = (const float*)d_in[1];
    const float* sinb = (const float*)d_in[2];
    const float* Wq  = (const float*)d_in[4];
    const float* bq  = (const float*)d_in[5];
    const float* Wk  = (const float*)d_in[6];
    const float* bk  = (const float*)d_in[7];
    const float* Wv  = (const float*)d_in[8];
    const float* bv  = (const float*)d_in[9];
    const float* Wo  = (const float*)d_in[10];
    const float* bo  = (const float*)d_in[11];
    const float* g1  = (const float*)d_in[12];
    const float* b1n = (const float*)d_in[13];
    const float* g2  = (const float*)d_in[14];
    const float* b2n = (const float*)d_in[15];
    const float* W1  = (const float*)d_in[16];
    const float* bf1 = (const float*)d_in[17];
    const float* W2  = (const float*)d_in[18];
    const float* bf2 = (const float*)d_in[19];
    float* out = (float*)d_out;

    float *h, *tmp, *q, *k, *v, *attn, *x2, *ffn;
    float *wq_t, *wk_t, *wv_t, *wo_t, *w1_t, *w2_t;
    cudaGetSymbolAddress((void**)&h,    g_h);
    cudaGetSymbolAddress((void**)&tmp,  g_tmp);
    cudaGetSymbolAddress((void**)&q,    g_q);
    cudaGetSymbolAddress((void**)&k,    g_k);
    cudaGetSymbolAddress((void**)&v,    g_v);
    cudaGetSymbolAddress((void**)&attn, g_attn);
    cudaGetSymbolAddress((void**)&x2,   g_x2);
    cudaGetSymbolAddress((void**)&ffn,  g_ffn);
    cudaGetSymbolAddress((void**)&wq_t, g_wq_t);
    cudaGetSymbolAddress((void**)&wk_t, g_wk_t);
    cudaGetSymbolAddress((void**)&wv_t, g_wv_t);
    cudaGetSymbolAddress((void**)&wo_t, g_wo_t);
    cudaGetSymbolAddress((void**)&w1_t, g_w1_t);
    cudaGetSymbolAddress((void**)&w2_t, g_w2_t);

    int attnSmem = (2 * 128 + 2 * 64) * ASTR * (int)sizeof(float);
    cudaFuncSetAttribute(attn_tc, cudaFuncAttributeMaxDynamicSharedMemorySize, attnSmem);

    // weight prep
    dim3 pblk(128);
    prep_w<<<dim3(Dc/16, Dc/128), pblk>>>(Wq, wq_t, Dc, Dc);
    prep_w<<<dim3(Dc/16, Dc/128), pblk>>>(Wk, wk_t, Dc, Dc);
    prep_w<<<dim3(Dc/16, Dc/128), pblk>>>(Wv, wv_t, Dc, Dc);
    prep_w<<<dim3(Dc/16, Dc/128), pblk>>>(Wo, wo_t, Dc, Dc);
    prep_w<<<dim3(Dc/16, 4*Dc/128), pblk>>>(W1, w1_t, Dc, 4*Dc);
    prep_w<<<dim3(4*Dc/16, Dc/128), pblk>>>(W2, w2_t, 4*Dc, Dc);

    dim3 gblk(128);
    dim3 blk(256);
    dim3 gProj(Dc / 128, ROWS / 128);
    dim3 gFfn1(4 * Dc / 128, ROWS / 128);
    int ropeBlocks = (Bc * Tc * Hc * NBc) / 256;

    ln_kernel<<<ROWS, blk>>>(x, g1, b1n, h);
    gemm_tc<false><<<gProj, gblk>>>(h, wq_t, bq, nullptr, tmp, ROWS, Dc, Dc);
    rope_kernel<<<ropeBlocks, blk>>>(tmp, cosb, sinb, q, 1);
    gemm_tc<false><<<gProj, gblk>>>(h, wk_t, bk, nullptr, tmp, ROWS, Dc, Dc);
    rope_kernel<<<ropeBlocks, blk>>>(tmp, cosb, sinb, k, 1);
    gemm_tc<false><<<gProj, gblk>>>(h, wv_t, bv, nullptr, tmp, ROWS, Dc, Dc);
    rope_kernel<<<ropeBlocks, blk>>>(tmp, cosb, sinb, v, 0);

    dim3 gAttn(Tc / 128, Bc * Hc);
    attn_tc<<<gAttn, blk, attnSmem>>>(q, k, v, attn);

    gemm_tc<false><<<gProj, gblk>>>(attn, wo_t, bo, x, x2, ROWS, Dc, Dc);
    ln_kernel<<<ROWS, blk>>>(x2, g2, b2n, h);
    gemm_tc<true><<<gFfn1, gblk>>>(h, w1_t, bf1, nullptr, ffn, ROWS, 4 * Dc, Dc);
    gemm_tc<false><<<gProj, gblk>>>(ffn, w2_t, bf2, x2, out, ROWS, Dc, 4 * Dc);
}

// round 6
// speedup vs baseline: 1.7845x; 1.7845x over previous
#include <cuda_runtime.h>
#include <math.h>
#include <stdint.h>

// Problem constants
#define Bc 2
#define Tc 2048
#define Dc 1024
#define Hc 16
#define DHc 64
#define NBc 32
#define ROWS (Bc*Tc)          // 4096

// ---------------- scratch ----------------
__device__ float g_h   [ (size_t)ROWS * Dc ];
__device__ float g_q   [ (size_t)ROWS * Dc ];
__device__ float g_k   [ (size_t)ROWS * Dc ];
__device__ float g_v   [ (size_t)ROWS * Dc ];
__device__ float g_attn[ (size_t)ROWS * Dc ];
__device__ float g_x2  [ (size_t)ROWS * Dc ];
__device__ float g_ffn [ (size_t)ROWS * 4 * Dc ];
// pre-swizzled weights (tf32): [n_tile][k_tile][2048]
__device__ float g_wq_t[ (size_t)Dc * Dc ];
__device__ float g_wk_t[ (size_t)Dc * Dc ];
__device__ float g_wv_t[ (size_t)Dc * Dc ];
__device__ float g_wo_t[ (size_t)Dc * Dc ];
__device__ float g_w1_t[ (size_t)Dc * 4 * Dc ];
__device__ float g_w2_t[ (size_t)Dc * 4 * Dc ];

// ---------------- helpers ----------------
__device__ __forceinline__ float to_tf32(float x)
{
    uint32_t u;
    asm("cvt.rna.tf32.f32 %0, %1;" : "=r"(u) : "f"(x));
    return __uint_as_float(u);
}

__device__ __forceinline__ void mma8(float c[4],
    float a0, float a1, float a2, float a3, float b0, float b1)
{
    asm volatile(
        "mma.sync.aligned.m16n8k8.row.col.f32.tf32.tf32.f32 "
        "{%0,%1,%2,%3}, {%4,%5,%6,%7}, {%8,%9}, {%0,%1,%2,%3};"
        : "+f"(c[0]), "+f"(c[1]), "+f"(c[2]), "+f"(c[3])
        : "r"(__float_as_uint(a0)), "r"(__float_as_uint(a1)),
          "r"(__float_as_uint(a2)), "r"(__float_as_uint(a3)),
          "r"(__float_as_uint(b0)), "r"(__float_as_uint(b1)));
}

__device__ __forceinline__ int a_idx(int r, int k, int stride)
{
    return r * stride + ((k >> 4) << 4) + 4 * (((k & 3) ^ (r & 3))) + ((k >> 2) & 3);
}
__device__ __forceinline__ int b_idx(int n, int k, int stride)
{
    return n * stride + ((k >> 4) << 4)
         + 4 * (((k & 3) ^ (n & 3) ^ ((n >> 2) & 3))) + ((k >> 2) & 3);
}

__device__ __forceinline__ void cp_async16(uint32_t smem_dst, const void* gptr)
{
    asm volatile("cp.async.cg.shared.global [%0], [%1], 16;"
                 :: "r"(smem_dst), "l"(gptr));
}
__device__ __forceinline__ void cp_commit()  { asm volatile("cp.async.commit_group;"); }
__device__ __forceinline__ void cp_wait0()   { asm volatile("cp.async.wait_group 0;" ::: "memory"); }

__device__ __forceinline__ float gelu_f(float v)
{
    return 0.5f * v * (1.0f + erff(v * 0.70710678118654752f));
}

// ---------------- weight prep (fast): W[K][N] -> swizzled tf32 tiles ----------
__global__ void __launch_bounds__(256) prep_w(const float* __restrict__ W,
                                              float* __restrict__ out, int K, int N)
{
    __shared__ float s[16][132];
    int kt = blockIdx.x, nt = blockIdx.y, tid = threadIdx.x;
    int ktiles = K / 16;
    #pragma unroll
    for (int j = 0; j < 2; j++) {
        int u = tid + 256 * j;            // 512 float4 units
        int kk = u >> 5, nc = (u & 31) * 4;
        float4 w = *(const float4*)&W[(size_t)(kt * 16 + kk) * N + nt * 128 + nc];
        s[kk][nc + 0] = to_tf32(w.x);
        s[kk][nc + 1] = to_tf32(w.y);
        s[kk][nc + 2] = to_tf32(w.z);
        s[kk][nc + 3] = to_tf32(w.w);
    }
    __syncthreads();
    float* dst = out + ((size_t)nt * ktiles + kt) * 2048;
    #pragma unroll
    for (int j = 0; j < 2; j++) {
        int u = tid + 256 * j;            // 512 output float4 units
        int nl = u >> 2, g = u & 3;
        int c = g ^ (nl & 3);
        float4 v = make_float4(s[c][nl], s[c + 4][nl], s[c + 8][nl], s[c + 12][nl]);
        *(float4*)&dst[u * 4] = v;
    }
}

// ---------------- LayerNorm ----------------
__global__ void __launch_bounds__(256) ln_kernel(const float* __restrict__ x,
                                                 const float* __restrict__ g,
                                                 const float* __restrict__ b,
                                                 float* __restrict__ o)
{
    __shared__ float sred[16];
    int row = blockIdx.x;
    int tid = threadIdx.x;
    const float* xr = x + (size_t)row * Dc;
    float4 v = *(const float4*)&xr[tid * 4];
    float s  = v.x + v.y + v.z + v.w;
    float s2 = v.x*v.x + v.y*v.y + v.z*v.z + v.w*v.w;
    #pragma unroll
    for (int off = 16; off; off >>= 1) {
        s  += __shfl_xor_sync(0xffffffffu, s,  off);
        s2 += __shfl_xor_sync(0xffffffffu, s2, off);
    }
    if ((tid & 31) == 0) { sred[tid >> 5] = s; sred[8 + (tid >> 5)] = s2; }
    __syncthreads();
    float S = 0.f, S2 = 0.f;
    #pragma unroll
    for (int i = 0; i < 8; i++) { S += sred[i]; S2 += sred[8 + i]; }
    float mean = S * (1.0f / Dc);
    float var  = S2 * (1.0f / Dc) - mean * mean;
    float rstd = rsqrtf(var + 1e-5f);
    float4 gv = *(const float4*)&g[tid * 4];
    float4 bv = *(const float4*)&b[tid * 4];
    float4 ov;
    ov.x = (v.x - mean) * rstd * gv.x + bv.x;
    ov.y = (v.y - mean) * rstd * gv.y + bv.y;
    ov.z = (v.z - mean) * rstd * gv.z + bv.z;
    ov.w = (v.w - mean) * rstd * gv.w + bv.w;
    *(float4*)&o[(size_t)row * Dc + tid * 4] = ov;
}

// =====================  GEMM mainloop building blocks  ========================
// CTA 128x128, 256 threads, 8 warps (2 x 4), warp tile 64x32.
// A: LDG->cvt->STS (r3-proven). B: cp.async of pre-swizzled tf32 tiles.

#define GEMM_PROLOGUE()                                                          \
    int tid  = threadIdx.x;                                                      \
    int lane = tid & 31;                                                         \
    int warp = tid >> 5;                                                         \
    int q4 = lane & 3, rr = lane >> 2;                                           \
    int wm = (warp & 1) * 64;                                                    \
    int wn = (warp >> 1) * 32;                                                   \
    int ar = tid >> 2;                                                           \
    int ac = (tid & 3) * 4;                                                      \
    int axor = ar & 3;                                                           \
    int ap0 = 4 * ((0 ^ axor)) + (tid & 3);                                      \
    int ap1 = 4 * ((1 ^ axor)) + (tid & 3);                                      \
    int ap2 = 4 * ((2 ^ axor)) + (tid & 3);                                      \
    int ap3 = 4 * ((3 ^ axor)) + (tid & 3);                                      \
    uint32_t sB_u32 = (uint32_t)__cvta_generic_to_shared(&sB[0][0]);             \
    float acc[4][4][4];                                                          \
    _Pragma("unroll") for (int i = 0; i < 4; i++)                                \
        _Pragma("unroll") for (int j = 0; j < 4; j++)                            \
            _Pragma("unroll") for (int r = 0; r < 4; r++) acc[i][j][r] = 0.f;    \
    int agrp = 4 * (q4 ^ (rr & 3));

#define GEMM_LOAD_TILE0()                                                        \
    {                                                                            \
        cp_async16(sB_u32 + tid * 32,       BtBase + tid * 8);                   \
        cp_async16(sB_u32 + tid * 32 + 16,  BtBase + tid * 8 + 4);               \
        cp_commit();                                                             \
        float4 a0 = *(const float4*)(Aptr);                                      \
        float4 a1 = *(const float4*)(Aptr + (size_t)64 * K);                     \
        sA[0][ar * 16 + ap0]        = to_tf32(a0.x);                             \
        sA[0][ar * 16 + ap1]        = to_tf32(a0.y);                             \
        sA[0][ar * 16 + ap2]        = to_tf32(a0.z);                             \
        sA[0][ar * 16 + ap3]        = to_tf32(a0.w);                             \
        sA[0][(ar + 64) * 16 + ap0] = to_tf32(a1.x);                             \
        sA[0][(ar + 64) * 16 + ap1] = to_tf32(a1.y);                             \
        sA[0][(ar + 64) * 16 + ap2] = to_tf32(a1.z);                             \
        sA[0][(ar + 64) * 16 + ap3] = to_tf32(a1.w);                             \
        cp_wait0();                                                              \
    }                                                                            \
    __syncthreads();

#define GEMM_MAINLOOP()                                                          \
    for (int t = 0; t < ktiles; t++) {                                           \
        int buf = t & 1;                                                         \
        bool pref = (t + 1 < ktiles);                                            \
        float4 a0, a1;                                                           \
        if (pref) {                                                              \
            int nb = buf ^ 1;                                                    \
            const float* Bp = BtBase + (size_t)(t + 1) * 2048;                   \
            cp_async16(sB_u32 + nb * 8192 + tid * 32,      Bp + tid * 8);        \
            cp_async16(sB_u32 + nb * 8192 + tid * 32 + 16, Bp + tid * 8 + 4);    \
            cp_commit();                                                         \
            const float* Ap = Aptr + (t + 1) * 16;                               \
            a0 = *(const float4*)(Ap);                                           \
            a1 = *(const float4*)(Ap + (size_t)64 * K);                          \
        }                                                                        \
        float4 fb[4];                                                            \
        _Pragma("unroll") for (int ni = 0; ni < 4; ni++) {                       \
            int n0 = wn + ni * 8 + rr;                                           \
            fb[ni] = *(float4*)&sB[buf][n0 * 16 + 4 * (q4 ^ (n0 & 3))];          \
        }                                                                        \
        _Pragma("unroll") for (int mi = 0; mi < 4; mi++) {                       \
            int r0 = wm + mi * 16 + rr;                                          \
            float4 lo = *(float4*)&sA[buf][r0 * 16 + agrp];                      \
            float4 hi = *(float4*)&sA[buf][(r0 + 8) * 16 + agrp];                \
            _Pragma("unroll") for (int ni = 0; ni < 4; ni++) {                   \
                mma8(acc[mi][ni], lo.x, hi.x, lo.y, hi.y, fb[ni].x, fb[ni].y);   \
                mma8(acc[mi][ni], lo.z, hi.z, lo.w, hi.w, fb[ni].z, fb[ni].w);   \
            }                                                                    \
        }                                                                        \
        if (pref) {                                                              \
            int nb = buf ^ 1;                                                    \
            sA[nb][ar * 16 + ap0]        = to_tf32(a0.x);                        \
            sA[nb][ar * 16 + ap1]        = to_tf32(a0.y);                        \
            sA[nb][ar * 16 + ap2]        = to_tf32(a0.z);                        \
            sA[nb][ar * 16 + ap3]        = to_tf32(a0.w);                        \
            sA[nb][(ar + 64) * 16 + ap0] = to_tf32(a1.x);                        \
            sA[nb][(ar + 64) * 16 + ap1] = to_tf32(a1.y);                        \
            sA[nb][(ar + 64) * 16 + ap2] = to_tf32(a1.z);                        \
            sA[nb][(ar + 64) * 16 + ap3] = to_tf32(a1.w);                        \
            cp_wait0();                                                          \
        }                                                                        \
        __syncthreads();                                                         \
    }

// ---------------- generic GEMM (plain / gelu), row-major output --------------
template<bool GELU>
__global__ void __launch_bounds__(256) gemm_tc(
    const float* __restrict__ A, const float* __restrict__ Bt,
    const float* __restrict__ bias, const float* __restrict__ res,
    float* __restrict__ C, int M, int N, int K)
{
    __shared__ float sA[2][2048];
    __shared__ float sB[2][2048];
    int bm = blockIdx.y * 128, bn = blockIdx.x * 128;
    int ktiles = K / 16;

    GEMM_PROLOGUE();
    const float* Aptr = A + (size_t)(bm + ar) * K + ac;
    const float* BtBase = Bt + ((size_t)(bn >> 7) * ktiles) * 2048;
    GEMM_LOAD_TILE0();
    GEMM_MAINLOOP();

    #pragma unroll
    for (int mi = 0; mi < 4; mi++) {
        int row = bm + wm + mi * 16 + rr;
        #pragma unroll
        for (int ni = 0; ni < 4; ni++) {
            int col = bn + wn + ni * 8 + 2 * q4;
            float2 bb = *(const float2*)&bias[col];
            float2 r01 = make_float2(acc[mi][ni][0] + bb.x, acc[mi][ni][1] + bb.y);
            float2 r23 = make_float2(acc[mi][ni][2] + bb.x, acc[mi][ni][3] + bb.y);
            if (GELU) {
                r01.x = gelu_f(r01.x); r01.y = gelu_f(r01.y);
                r23.x = gelu_f(r23.x); r23.y = gelu_f(r23.y);
            }
            if (res) {
                float2 v0 = *(const float2*)&res[(size_t)row * N + col];
                float2 v1 = *(const float2*)&res[(size_t)(row + 8) * N + col];
                r01.x += v0.x; r01.y += v0.y;
                r23.x += v1.x; r23.y += v1.y;
            }
            *(float2*)&C[(size_t)row * N + col] = r01;
            *(float2*)&C[(size_t)(row + 8) * N + col] = r23;
        }
    }
}

// ---------------- fused QKV GEMM: RoPE + [B,T,D]->[B,H,T,DH] epilogue --------
__global__ void __launch_bounds__(256) gemm_qkv(
    const float* __restrict__ A,
    const float* __restrict__ wq_t, const float* __restrict__ wk_t,
    const float* __restrict__ wv_t,
    const float* __restrict__ bq, const float* __restrict__ bk,
    const float* __restrict__ bv,
    const float* __restrict__ cosb, const float* __restrict__ sinb,
    float* __restrict__ Qo, float* __restrict__ Ko, float* __restrict__ Vo)
{
    __shared__ float sA[2][2048];
    __shared__ float sB[2][2048];
    const int K = Dc;
    int which = blockIdx.x >> 3;          // 0=Q 1=K 2=V
    int bnl   = (blockIdx.x & 7) * 128;
    int bm    = blockIdx.y * 128;
    int ktiles = K / 16;

    const float* Bt   = (which == 0) ? wq_t : (which == 1) ? wk_t : wv_t;
    const float* bias = (which == 0) ? bq   : (which == 1) ? bk   : bv;
    float*       Out  = (which == 0) ? Qo   : (which == 1) ? Ko   : Vo;

    GEMM_PROLOGUE();
    const float* Aptr = A + (size_t)(bm + ar) * K + ac;
    const float* BtBase = Bt + ((size_t)(bnl >> 7) * ktiles) * 2048;
    GEMM_LOAD_TILE0();
    GEMM_MAINLOOP();

    // epilogue: bias, optional RoPE, write transposed [B,H,T,DH]
    #pragma unroll
    for (int mi = 0; mi < 4; mi++) {
        int row = bm + wm + mi * 16 + rr;         // and row+8
        int t0 = row & (Tc - 1);
        int bI = row >> 11;
        #pragma unroll
        for (int ni = 0; ni < 4; ni++) {
            int col = bnl + wn + ni * 8 + 2 * q4;
            int hh = col >> 6;
            int dh = col & 63;
            int ii = dh >> 1;
            float2 bb = *(const float2*)&bias[col];
            float p0 = acc[mi][ni][0] + bb.x, p1 = acc[mi][ni][1] + bb.y;
            float p2 = acc[mi][ni][2] + bb.x, p3 = acc[mi][ni][3] + bb.y;
            size_t basebh = ((size_t)bI * Hc + hh) * Tc;
            if (which < 2) {
                size_t ci0 = (basebh + t0) * NBc + ii;
                size_t ci1 = (basebh + t0 + 8) * NBc + ii;
                float c0 = cosb[ci0], s0 = sinb[ci0];
                float c1 = cosb[ci1], s1 = sinb[ci1];
                float o1 = p0 * c0 - p1 * s0, o2 = p0 * s0 + p1 * c0;
                float o3 = p2 * c1 - p3 * s1, o4 = p2 * s1 + p3 * c1;
                p0 = o1; p1 = o2; p2 = o3; p3 = o4;
            }
            *(float2*)&Out[(basebh + t0) * 64 + dh]     = make_float2(p0, p1);
            *(float2*)&Out[(basebh + t0 + 8) * 64 + dh] = make_float2(p2, p3);
        }
    }
}

// ---------------- Tensor-core flash attention (round-3, proven) --------------
#define ASTR 80

__global__ void __launch_bounds__(256) attn_tc(
    const float* __restrict__ Q, const float* __restrict__ K,
    const float* __restrict__ V, float* __restrict__ O)
{
    extern __shared__ float sm[];
    float* sQ  = sm;
    float* sP  = sm + 128 * ASTR;
    float* sKt = sm + 256 * ASTR;
    float* sVt = sKt + 64 * ASTR;

    int tid = threadIdx.x, lane = tid & 31, warp = tid >> 5;
    int q4 = lane & 3, rr = lane >> 2;
    int bh = blockIdx.y;
    int b = bh >> 4, h = bh & 15;
    int qb = gridDim.x - 1 - blockIdx.x;

    const float* Qb = Q + ((size_t)bh * Tc + (size_t)qb * 128) * DHc;
    const float* Kb = K + (size_t)bh * Tc * DHc;
    const float* Vb = V + (size_t)bh * Tc * DHc;

    #pragma unroll
    for (int jj = 0; jj < 8; jj++) {
        int f4 = tid + 256 * jj;
        int r = f4 >> 4, kb = (f4 & 15) * 4;
        float4 qv = *(const float4*)&Qb[r * 64 + kb];
        sQ[a_idx(r, kb + 0, ASTR)] = to_tf32(qv.x * 0.125f);
        sQ[a_idx(r, kb + 1, ASTR)] = to_tf32(qv.y * 0.125f);
        sQ[a_idx(r, kb + 2, ASTR)] = to_tf32(qv.z * 0.125f);
        sQ[a_idx(r, kb + 3, ASTR)] = to_tf32(qv.w * 0.125f);
    }

    float m0 = -1e30f, m1 = -1e30f, l0 = 0.f, l1 = 0.f;
    float o[8][4];
    #pragma unroll
    for (int ni = 0; ni < 8; ni++)
        #pragma unroll
        for (int j = 0; j < 4; j++) o[ni][j] = 0.f;

    int r0 = 16 * warp + rr;
    int rowg = qb * 128 + r0;
    int agrp = 4 * (q4 ^ (r0 & 3));

    int nkt = 2 * qb + 2;
    for (int kt = 0; kt < nkt; kt++) {
        __syncthreads();
        const float* Kt = Kb + (size_t)kt * 64 * DHc;
        const float* Vt = Vb + (size_t)kt * 64 * DHc;
        #pragma unroll
        for (int jj = 0; jj < 4; jj++) {
            int f4 = tid + 256 * jj;
            int n = f4 >> 4, kb = (f4 & 15) * 4;
            float4 kv = *(const float4*)&Kt[n * 64 + kb];
            sKt[b_idx(n, kb + 0, ASTR)] = to_tf32(kv.x);
            sKt[b_idx(n, kb + 1, ASTR)] = to_tf32(kv.y);
            sKt[b_idx(n, kb + 2, ASTR)] = to_tf32(kv.z);
            sKt[b_idx(n, kb + 3, ASTR)] = to_tf32(kv.w);
            float4 vv = *(const float4*)&Vt[n * 64 + kb];
            sVt[b_idx(kb + 0, n, ASTR)] = to_tf32(vv.x);
            sVt[b_idx(kb + 1, n, ASTR)] = to_tf32(vv.y);
            sVt[b_idx(kb + 2, n, ASTR)] = to_tf32(vv.z);
            sVt[b_idx(kb + 3, n, ASTR)] = to_tf32(vv.w);
        }
        __syncthreads();

        float s[8][4];
        #pragma unroll
        for (int ni = 0; ni < 8; ni++)
            #pragma unroll
            for (int j = 0; j < 4; j++) s[ni][j] = 0.f;

        #pragma unroll
        for (int ch = 0; ch < 4; ch++) {
            float4 lo = *(float4*)&sQ[r0 * ASTR + ch * 16 + agrp];
            float4 hi = *(float4*)&sQ[(r0 + 8) * ASTR + ch * 16 + agrp];
            #pragma unroll
            for (int ni = 0; ni < 8; ni++) {
                int n0 = ni * 8 + rr;
                float4 fb = *(float4*)&sKt[n0 * ASTR + ch * 16
                                + 4 * (q4 ^ (n0 & 3) ^ ((n0 >> 2) & 3))];
                mma8(s[ni], lo.x, hi.x, lo.y, hi.y, fb.x, fb.y);
                mma8(s[ni], lo.z, hi.z, lo.w, hi.w, fb.z, fb.w);
            }
        }

        if (kt >= 2 * qb) {
            #pragma unroll
            for (int ni = 0; ni < 8; ni++) {
                int colg = kt * 64 + ni * 8 + 2 * q4;
                if (colg     > rowg)     s[ni][0] = -1e30f;
                if (colg + 1 > rowg)     s[ni][1] = -1e30f;
                if (colg     > rowg + 8) s[ni][2] = -1e30f;
                if (colg + 1 > rowg + 8) s[ni][3] = -1e30f;
            }
        }

        float mx0 = -1e30f, mx1 = -1e30f;
        #pragma unroll
        for (int ni = 0; ni < 8; ni++) {
            mx0 = fmaxf(mx0, fmaxf(s[ni][0], s[ni][1]));
            mx1 = fmaxf(mx1, fmaxf(s[ni][2], s[ni][3]));
        }
        mx0 = fmaxf(mx0, __shfl_xor_sync(0xffffffffu, mx0, 1));
        mx0 = fmaxf(mx0, __shfl_xor_sync(0xffffffffu, mx0, 2));
        mx1 = fmaxf(mx1, __shfl_xor_sync(0xffffffffu, mx1, 1));
        mx1 = fmaxf(mx1, __shfl_xor_sync(0xffffffffu, mx1, 2));
        float mn0 = fmaxf(m0, mx0), mn1 = fmaxf(m1, mx1);
        float al0 = __expf(m0 - mn0), al1 = __expf(m1 - mn1);
        m0 = mn0; m1 = mn1;

        float sum0 = 0.f, sum1 = 0.f;
        #pragma unroll
        for (int ni = 0; ni < 8; ni++) {
            int kl = ni * 8 + 2 * q4;
            float p0 = __expf(s[ni][0] - m0);
            float p1 = __expf(s[ni][1] - m0);
            float p2 = __expf(s[ni][2] - m1);
            float p3 = __expf(s[ni][3] - m1);
            sum0 += p0 + p1; sum1 += p2 + p3;
            sP[a_idx(r0,     kl,     ASTR)] = p0;
            sP[a_idx(r0,     kl + 1, ASTR)] = p1;
            sP[a_idx(r0 + 8, kl,     ASTR)] = p2;
            sP[a_idx(r0 + 8, kl + 1, ASTR)] = p3;
        }
        sum0 += __shfl_xor_sync(0xffffffffu, sum0, 1);
        sum0 += __shfl_xor_sync(0xffffffffu, sum0, 2);
        sum1 += __shfl_xor_sync(0xffffffffu, sum1, 1);
        sum1 += __shfl_xor_sync(0xffffffffu, sum1, 2);
        l0 = l0 * al0 + sum0;
        l1 = l1 * al1 + sum1;

        #pragma unroll
        for (int ni = 0; ni < 8; ni++) {
            o[ni][0] *= al0; o[ni][1] *= al0;
            o[ni][2] *= al1; o[ni][3] *= al1;
        }
        __syncwarp();

        #pragma unroll
        for (int ch = 0; ch < 4; ch++) {
            float4 lo = *(float4*)&sP[r0 * ASTR + ch * 16 + agrp];
            float4 hi = *(float4*)&sP[(r0 + 8) * ASTR + ch * 16 + agrp];
            #pragma unroll
            for (int ni = 0; ni < 8; ni++) {
                int n0 = ni * 8 + rr;
                float4 fb = *(float4*)&sVt[n0 * ASTR + ch * 16
                                + 4 * (q4 ^ (n0 & 3) ^ ((n0 >> 2) & 3))];
                mma8(o[ni], lo.x, hi.x, lo.y, hi.y, fb.x, fb.y);
                mma8(o[ni], lo.z, hi.z, lo.w, hi.w, fb.z, fb.w);
            }
        }
    }

    float inv0 = 1.f / l0, inv1 = 1.f / l1;
    int t0 = qb * 128 + r0;
    #pragma unroll
    for (int ni = 0; ni < 8; ni++) {
        int dh = ni * 8 + 2 * q4;
        *(float2*)&O[((((size_t)b * Tc + t0) * Hc + h) * DHc) + dh] =
            make_float2(o[ni][0] * inv0, o[ni][1] * inv0);
        *(float2*)&O[((((size_t)b * Tc + t0 + 8) * Hc + h) * DHc) + dh] =
            make_float2(o[ni][2] * inv1, o[ni][3] * inv1);
    }
}

// ---------------- launch ----------------
extern "C" void kernel_launch(void* const* d_in, const int* in_sizes, int n_in,
                              void* d_out, int out_size)
{
    const float* x    = (const float*)d_in[0];
    const float* cosb = (const float*)d_in[1];
    const float* sinb = (const float*)d_in[2];
    const float* Wq  = (const float*)d_in[4];
    const float* bq  = (const float*)d_in[5];
    const float* Wk  = (const float*)d_in[6];
    const float* bk  = (const float*)d_in[7];
    const float* Wv  = (const float*)d_in[8];
    const float* bv  = (const float*)d_in[9];
    const float* Wo  = (const float*)d_in[10];
    const float* bo  = (const float*)d_in[11];
    const float* g1  = (const float*)d_in[12];
    const float* b1n = (const float*)d_in[13];
    const float* g2  = (const float*)d_in[14];
    const float* b2n = (const float*)d_in[15];
    const float* W1  = (const float*)d_in[16];
    const float* bf1 = (const float*)d_in[17];
    const float* W2  = (const float*)d_in[18];
    const float* bf2 = (const float*)d_in[19];
    float* out = (float*)d_out;

    float *h, *q, *k, *v, *attn, *x2, *ffn;
    float *wq_t, *wk_t, *wv_t, *wo_t, *w1_t, *w2_t;
    cudaGetSymbolAddress((void**)&h,    g_h);
    cudaGetSymbolAddress((void**)&q,    g_q);
    cudaGetSymbolAddress((void**)&k,    g_k);
    cudaGetSymbolAddress((void**)&v,    g_v);
    cudaGetSymbolAddress((void**)&attn, g_attn);
    cudaGetSymbolAddress((void**)&x2,   g_x2);
    cudaGetSymbolAddress((void**)&ffn,  g_ffn);
    cudaGetSymbolAddress((void**)&wq_t, g_wq_t);
    cudaGetSymbolAddress((void**)&wk_t, g_wk_t);
    cudaGetSymbolAddress((void**)&wv_t, g_wv_t);
    cudaGetSymbolAddress((void**)&wo_t, g_wo_t);
    cudaGetSymbolAddress((void**)&w1_t, g_w1_t);
    cudaGetSymbolAddress((void**)&w2_t, g_w2_t);

    int attnSmem = (2 * 128 + 2 * 64) * ASTR * (int)sizeof(float);
    cudaFuncSetAttribute(attn_tc, cudaFuncAttributeMaxDynamicSharedMemorySize, attnSmem);

    // weight prep (fast version)
    dim3 pblk(256);
    prep_w<<<dim3(Dc/16, Dc/128), pblk>>>(Wq, wq_t, Dc, Dc);
    prep_w<<<dim3(Dc/16, Dc/128), pblk>>>(Wk, wk_t, Dc, Dc);
    prep_w<<<dim3(Dc/16, Dc/128), pblk>>>(Wv, wv_t, Dc, Dc);
    prep_w<<<dim3(Dc/16, Dc/128), pblk>>>(Wo, wo_t, Dc, Dc);
    prep_w<<<dim3(Dc/16, 4*Dc/128), pblk>>>(W1, w1_t, Dc, 4*Dc);
    prep_w<<<dim3(4*Dc/16, Dc/128), pblk>>>(W2, w2_t, 4*Dc, Dc);

    dim3 blk(256);
    dim3 gProj(Dc / 128, ROWS / 128);        // (8, 32)
    dim3 gQkv(3 * Dc / 128, ROWS / 128);     // (24, 32)
    dim3 gFfn1(4 * Dc / 128, ROWS / 128);    // (32, 32)

    // 1. h = LN(x)
    ln_kernel<<<ROWS, blk>>>(x, g1, b1n, h);
    // 2. fused QKV projection + RoPE + transpose
    gemm_qkv<<<gQkv, blk>>>(h, wq_t, wk_t, wv_t, bq, bk, bv, cosb, sinb, q, k, v);
    // 3. causal flash attention
    dim3 gAttn(Tc / 128, Bc * Hc);
    attn_tc<<<gAttn, blk, attnSmem>>>(q, k, v, attn);
    // 4. x2 = x + attn @ Wo + bo
    gemm_tc<false><<<gProj, blk>>>(attn, wo_t, bo, x, x2, ROWS, Dc, Dc);
    // 5. h = LN(x2)
    ln_kernel<<<ROWS, blk>>>(x2, g2, b2n, h);
    // 6. ffn = gelu(h @ W1 + bf1)
    gemm_tc<true><<<gFfn1, blk>>>(h, w1_t, bf1, nullptr, ffn, ROWS, 4 * Dc, Dc);
    // 7. out = x2 + ffn @ W2 + bf2
    gemm_tc<false><<<gProj, blk>>>(ffn, w2_t, bf2, x2, out, ROWS, Dc, 4 * Dc);
}